// round 11
// baseline (speedup 1.0000x reference)
#include <cuda_runtime.h>
#include <math.h>

// Shapes fixed by the reference: B=4, M=64, K=32, C=256
//   tiles = B*M = 256 (one per (b,m))
//   p  : [256][1024]  pooled, column-major columns as rows (K-contiguous)
//   hp : [2][256][512] split-K partials of W1 @ p
//   h  : [256][512]   gelu(hp0+hp1)
//   e  : [256][1024]  sigmoid(W2 @ h)
// Output buffer = out (B,M,K,C) followed by adj (B,M,K,K).

__device__ float g_p [256*1024];
__device__ float g_hp[2*256*512];
__device__ float g_h [256*512];
__device__ float g_e [256*1024];

#define NEGBIG -9000000000000000.0f

// ---------------------------------------------------------------------------
// Kernel 1: per-tile stats -> adj (to d_out) and pooled -> g_p
// cov_raw_ij = sum_c a*b - 256*mu_i*mu_j ; adj = cov_raw/sqrt(diag_i*diag_j)
// pooled_ij  = 0.5*mu_i + mu_j - (sum_{c: x_i,c==x_j,c} x_j,c)/512
// ---------------------------------------------------------------------------
__global__ __launch_bounds__(256) void k_stats(const float* __restrict__ x,
                                               float* __restrict__ adj) {
    __shared__ float xs[32*257];   // padded: stride 257 -> conflict-free column access
    __shared__ float mu[32];
    __shared__ float rs[32];
    const int tile = blockIdx.x;
    const int tid  = threadIdx.x;
    const float* xt = x + (size_t)tile * 8192;

    for (int idx = tid; idx < 8192; idx += 256)
        xs[(idx >> 8)*257 + (idx & 255)] = xt[idx];
    __syncthreads();

    // row sums + sumsq: 8 threads per row
    {
        int r = tid >> 3, g = tid & 7;
        const float* row = xs + r*257 + g*32;
        float s = 0.f, s2 = 0.f;
        #pragma unroll
        for (int c = 0; c < 32; ++c) { float v = row[c]; s += v; s2 = fmaf(v, v, s2); }
        #pragma unroll
        for (int off = 4; off; off >>= 1) {
            s  += __shfl_down_sync(0xffffffffu, s,  off, 8);
            s2 += __shfl_down_sync(0xffffffffu, s2, off, 8);
        }
        if (g == 0) {
            float m = s * (1.0f/256.0f);
            mu[r] = m;
            rs[r] = 1.0f / sqrtf(s2 - 256.0f*m*m);
        }
    }
    __syncthreads();

    // pair loop: lane = j; each thread handles i in {w, w+8, w+16, w+24}
    const int w = tid >> 5, lane = tid & 31;
    const float* rowj = xs + lane*257;
    const float muj = mu[lane];
    const float rsj = rs[lane];

    float sab[4] = {0.f,0.f,0.f,0.f};
    float eqs[4] = {0.f,0.f,0.f,0.f};
    #pragma unroll 4
    for (int c = 0; c < 256; ++c) {
        float b = rowj[c];
        #pragma unroll
        for (int k = 0; k < 4; ++k) {
            float a = xs[(k*8 + w)*257 + c];   // warp-uniform broadcast
            sab[k] = fmaf(a, b, sab[k]);
            if (a == b) eqs[k] += b;           // exact equality (pos mask)
        }
    }
    #pragma unroll
    for (int k = 0; k < 4; ++k) {
        int i = k*8 + w;
        float mui = mu[i];
        float covraw = sab[k] - 256.0f*mui*muj;
        int o = i*32 + lane;
        adj[(size_t)tile*1024 + o] = covraw * rs[i] * rsj;
        g_p[(size_t)tile*1024 + o] = fmaf(eqs[k], -(1.0f/512.0f), 0.5f*mui + muj);
    }
}

// ---------------------------------------------------------------------------
// Generic tiled SGEMM: OUT[col][o] = dot(W[o][:], X[col][:]) over K-chunks.
// Tile 64(o) x 32(col), 256 threads, micro 4x2. k-transposed SMEM:
//   Ws[kk][o] (stride 68, 16B aligned), Xs[kk][col] (stride 34, 8B aligned)
// EPI==0: GEMM1 split-K partial (X=g_p, OUT=g_hp, ldw=ldx=1024, ldo=512)
// EPI==1: GEMM2 + sigmoid       (X=g_h, OUT=g_e,  ldw=ldx=512,  ldo=1024)
// ---------------------------------------------------------------------------
template<int EPI>
__global__ __launch_bounds__(256) void k_gemm(const float* __restrict__ W, int ksteps) {
    __shared__ float Ws[32][68];
    __shared__ float Xs[32][34];
    constexpr int LDW = (EPI == 0) ? 1024 : 512;
    constexpr int LDX = (EPI == 0) ? 1024 : 512;
    constexpr int LDO = (EPI == 0) ? 512  : 1024;
    const float* X   = (EPI == 0) ? g_p  : g_h;
    float*       OUT = (EPI == 0) ? g_hp : g_e;

    const int tid = threadIdx.x;
    const int o0 = blockIdx.x*64, c0 = blockIdx.y*32;
    const int kbase = blockIdx.z * (ksteps*32);
    const int to = tid & 15, tc = tid >> 4;   // micro: o = o0+to*4+{0..3}, col = c0+tc*2+{0,1}
    const int lo = tid >> 3, lf = tid & 7;    // loaders

    const float* wp0 = W + (size_t)(o0 + lo)      * LDW + kbase + lf*4;
    const float* wp1 = W + (size_t)(o0 + lo + 32) * LDW + kbase + lf*4;
    const float* xp  = X + (size_t)(c0 + lo)      * LDX + kbase + lf*4;

    float a00=0.f,a10=0.f,a20=0.f,a30=0.f,a01=0.f,a11=0.f,a21=0.f,a31=0.f;

    for (int kc = 0; kc < ksteps; ++kc) {
        float4 v0 = *(const float4*)(wp0 + kc*32);
        float4 v1 = *(const float4*)(wp1 + kc*32);
        float4 u  = *(const float4*)(xp  + kc*32);
        __syncthreads();
        int kk = lf*4;
        Ws[kk+0][lo]    = v0.x; Ws[kk+1][lo]    = v0.y; Ws[kk+2][lo]    = v0.z; Ws[kk+3][lo]    = v0.w;
        Ws[kk+0][lo+32] = v1.x; Ws[kk+1][lo+32] = v1.y; Ws[kk+2][lo+32] = v1.z; Ws[kk+3][lo+32] = v1.w;
        Xs[kk+0][lo] = u.x; Xs[kk+1][lo] = u.y; Xs[kk+2][lo] = u.z; Xs[kk+3][lo] = u.w;
        __syncthreads();
        #pragma unroll
        for (int k2 = 0; k2 < 32; ++k2) {
            const float4 a = *(const float4*)&Ws[k2][to*4];
            const float2 b = *(const float2*)&Xs[k2][tc*2];
            a00 = fmaf(a.x, b.x, a00); a10 = fmaf(a.y, b.x, a10);
            a20 = fmaf(a.z, b.x, a20); a30 = fmaf(a.w, b.x, a30);
            a01 = fmaf(a.x, b.y, a01); a11 = fmaf(a.y, b.y, a11);
            a21 = fmaf(a.z, b.y, a21); a31 = fmaf(a.w, b.y, a31);
        }
    }

    const int col = c0 + tc*2;
    const int o   = o0 + to*4;
    if (EPI == 1) {
        a00 = 1.0f/(1.0f+expf(-a00)); a10 = 1.0f/(1.0f+expf(-a10));
        a20 = 1.0f/(1.0f+expf(-a20)); a30 = 1.0f/(1.0f+expf(-a30));
        a01 = 1.0f/(1.0f+expf(-a01)); a11 = 1.0f/(1.0f+expf(-a11));
        a21 = 1.0f/(1.0f+expf(-a21)); a31 = 1.0f/(1.0f+expf(-a31));
    }
    size_t base;
    if (EPI == 0)
        base = ((size_t)blockIdx.z * (gridDim.y*32) + col) * LDO + o;  // [bz][col][512]
    else
        base = (size_t)col * LDO + o;                                  // [col][1024]
    *(float4*)(OUT + base)       = make_float4(a00, a10, a20, a30);
    *(float4*)(OUT + base + LDO) = make_float4(a01, a11, a21, a31);
}

// ---------------------------------------------------------------------------
// Combine split-K partials + exact GELU
// ---------------------------------------------------------------------------
__device__ __forceinline__ float gelu_f(float v) {
    return 0.5f * v * (1.0f + erff(v * 0.70710678118654752f));
}
__global__ __launch_bounds__(256) void k_glu(int n4) {
    int idx = blockIdx.x*256 + threadIdx.x;
    if (idx < n4) {
        const float4* hp = (const float4*)g_hp;
        float4 a = hp[idx];
        float4 b = hp[idx + n4];
        float4 r;
        r.x = gelu_f(a.x + b.x); r.y = gelu_f(a.y + b.y);
        r.z = gelu_f(a.z + b.z); r.w = gelu_f(a.w + b.w);
        ((float4*)g_h)[idx] = r;
    }
}

// ---------------------------------------------------------------------------
// Kernel 4: masked softmax over adj>0, then out = attn @ x (per tile)
// ---------------------------------------------------------------------------
__global__ __launch_bounds__(256) void k_attn(const float* __restrict__ x,
                                              const float* __restrict__ adj,
                                              float* __restrict__ out) {
    __shared__ float xs[32*257];
    __shared__ float at[32*36];     // at[j][i] = attn[i][j]; stride 36 -> 16B aligned rows
    const int tile = blockIdx.x;
    const int tid = threadIdx.x, w = tid >> 5, lane = tid & 31;
    const float* xt = x + (size_t)tile*8192;

    for (int idx = tid; idx < 8192; idx += 256)
        xs[(idx >> 8)*257 + (idx & 255)] = xt[idx];

    const float* er = g_e + (size_t)tile*1024;
    const float* ar = adj + (size_t)tile*1024;
    #pragma unroll
    for (int k = 0; k < 4; ++k) {
        int i = k*8 + w;
        float a = ar[i*32 + lane];
        float e = er[i*32 + lane];
        float v = (a > 0.f) ? e : NEGBIG;
        float mx = v;
        #pragma unroll
        for (int off = 16; off; off >>= 1) mx = fmaxf(mx, __shfl_xor_sync(0xffffffffu, mx, off));
        float pv = expf(v - mx);
        float s = pv;
        #pragma unroll
        for (int off = 16; off; off >>= 1) s += __shfl_xor_sync(0xffffffffu, s, off);
        at[lane*36 + i] = pv / s;
    }
    __syncthreads();

    const int c = tid;          // one channel per thread
    float acc[32];
    #pragma unroll
    for (int i = 0; i < 32; ++i) acc[i] = 0.f;
    for (int j = 0; j < 32; ++j) {
        float b = xs[j*257 + c];
        const float4* arow = (const float4*)(at + j*36);   // broadcast loads
        #pragma unroll
        for (int q = 0; q < 8; ++q) {
            float4 aw = arow[q];
            acc[q*4+0] = fmaf(aw.x, b, acc[q*4+0]);
            acc[q*4+1] = fmaf(aw.y, b, acc[q*4+1]);
            acc[q*4+2] = fmaf(aw.z, b, acc[q*4+2]);
            acc[q*4+3] = fmaf(aw.w, b, acc[q*4+3]);
        }
    }
    float* orow = out + (size_t)tile*8192 + c;
    #pragma unroll
    for (int i = 0; i < 32; ++i) orow[i*256] = acc[i];
}

// ---------------------------------------------------------------------------
extern "C" void kernel_launch(void* const* d_in, const int* in_sizes, int n_in,
                              void* d_out, int out_size) {
    const float* x  = (const float*)d_in[0];
    const float* W1 = (const float*)d_in[1];
    const float* W2 = (const float*)d_in[2];
    (void)n_in; (void)out_size;

    int B = in_sizes[0] / (64*32*256);     // = 4
    int tiles = B * 64;                    // = 256
    float* out = (float*)d_out;
    float* adj = out + (size_t)tiles * 8192;   // out first, then adj

    k_stats<<<tiles, 256>>>(x, adj);
    k_gemm<0><<<dim3(8, tiles/32, 2), 256>>>(W1, 16);   // 512x256xK=1024, split-K=2
    int n4 = (tiles*512) / 4;
    k_glu<<<(n4 + 255)/256, 256>>>(n4);
    k_gemm<1><<<dim3(16, tiles/32, 1), 256>>>(W2, 16);  // 1024x256xK=512 + sigmoid
    k_attn<<<tiles, 256>>>(x, adj, out);
}

// round 12
// speedup vs baseline: 1.0696x; 1.0696x over previous
#include <cuda_runtime.h>
#include <math.h>

// Shapes fixed by the reference: B=4, M=64, K=32, C=256
//   tiles = B*M = 256 (one per (b,m))
//   p  : [256][1024]   pooled (K*K contiguous per tile)
//   hp : [4][256][512] split-K partials of W1 @ p
//   h  : [256][512]    gelu(sum hp)
//   ep : [2][256][1024] split-K partials of W2 @ h (sigmoid applied in k_attn)
// Output buffer = out (B,M,K,C) followed by adj (B,M,K,K).

__device__ float g_p [256*1024];
__device__ float g_hp[4*256*512];
__device__ float g_h [256*512];
__device__ float g_ep[2*256*1024];

#define NEGBIG -9000000000000000.0f

// ---------------------------------------------------------------------------
// Kernel 1: per-tile stats -> adj (to d_out) and pooled -> g_p
// cov_raw_ij = sum_c a*b - 256*mu_i*mu_j ; adj = cov_raw/sqrt(diag_i*diag_j)
// pooled_ij  = 0.5*mu_i + mu_j - (sum_{c: x_i,c==x_j,c} x_j,c)/512
// ---------------------------------------------------------------------------
__global__ __launch_bounds__(256) void k_stats(const float* __restrict__ x,
                                               float* __restrict__ adj) {
    __shared__ float xs[32*257];   // stride 257 -> conflict-free strided access
    __shared__ float mu[32];
    __shared__ float rs[32];
    const int tile = blockIdx.x;
    const int tid  = threadIdx.x;
    const float* xt = x + (size_t)tile * 8192;

    for (int idx = tid; idx < 8192; idx += 256)
        xs[(idx >> 8)*257 + (idx & 255)] = xt[idx];
    __syncthreads();

    // row sums + sumsq: 8 threads per row
    {
        int r = tid >> 3, g = tid & 7;
        const float* row = xs + r*257 + g*32;
        float s = 0.f, s2 = 0.f;
        #pragma unroll
        for (int c = 0; c < 32; ++c) { float v = row[c]; s += v; s2 = fmaf(v, v, s2); }
        #pragma unroll
        for (int off = 4; off; off >>= 1) {
            s  += __shfl_down_sync(0xffffffffu, s,  off, 8);
            s2 += __shfl_down_sync(0xffffffffu, s2, off, 8);
        }
        if (g == 0) {
            float m = s * (1.0f/256.0f);
            mu[r] = m;
            rs[r] = 1.0f / sqrtf(s2 - 256.0f*m*m);
        }
    }
    __syncthreads();

    // pair loop: lane = j; each thread handles i in {w, w+8, w+16, w+24}
    const int w = tid >> 5, lane = tid & 31;
    const float* rowj = xs + lane*257;
    const float muj = mu[lane];
    const float rsj = rs[lane];

    float sab[4] = {0.f,0.f,0.f,0.f};
    float eqs[4] = {0.f,0.f,0.f,0.f};
    #pragma unroll 4
    for (int c = 0; c < 256; ++c) {
        float b = rowj[c];
        #pragma unroll
        for (int k = 0; k < 4; ++k) {
            float a = xs[(k*8 + w)*257 + c];   // warp-uniform broadcast
            sab[k] = fmaf(a, b, sab[k]);
            if (a == b) eqs[k] += b;           // exact equality (pos mask)
        }
    }
    #pragma unroll
    for (int k = 0; k < 4; ++k) {
        int i = k*8 + w;
        float mui = mu[i];
        float covraw = sab[k] - 256.0f*mui*muj;
        int o = i*32 + lane;
        adj[(size_t)tile*1024 + o] = covraw * rs[i] * rsj;
        g_p[(size_t)tile*1024 + o] = fmaf(eqs[k], -(1.0f/512.0f), 0.5f*mui + muj);
    }
}

// ---------------------------------------------------------------------------
// Tiled SGEMM, double-buffered SMEM, split-K along blockIdx.z.
// Tile 64(o) x 32(col), 256 threads, micro 4x2. k-transposed SMEM:
//   Ws[buf][kk][o] (stride 68), Xs[buf][kk][col] (stride 34)
// EPI==0: GEMM1 partial (X=g_p, OUT=g_hp, ld=1024, ldo=512)
// EPI==1: GEMM2 partial (X=g_h, OUT=g_ep, ld=512,  ldo=1024)
// One __syncthreads per 32-k chunk; global prefetch overlapped with compute.
// ---------------------------------------------------------------------------
template<int EPI>
__global__ __launch_bounds__(256) void k_gemm(const float* __restrict__ W, int ksteps) {
    __shared__ float Ws[2][32][68];
    __shared__ float Xs[2][32][34];
    constexpr int LDW = (EPI == 0) ? 1024 : 512;
    constexpr int LDX = (EPI == 0) ? 1024 : 512;
    constexpr int LDO = (EPI == 0) ? 512  : 1024;
    const float* X   = (EPI == 0) ? g_p  : g_h;
    float*       OUT = (EPI == 0) ? g_hp : g_ep;

    const int tid = threadIdx.x;
    const int o0 = blockIdx.x*64, c0 = blockIdx.y*32;
    const int kbase = blockIdx.z * (ksteps*32);
    const int to = tid & 15, tc = tid >> 4;   // micro: o = o0+to*4+{0..3}, col = c0+tc*2+{0,1}
    const int lo = tid >> 3, lf = tid & 7;    // loaders
    const int kk = lf*4;

    const float* wp0 = W + (size_t)(o0 + lo)      * LDW + kbase + lf*4;
    const float* wp1 = W + (size_t)(o0 + lo + 32) * LDW + kbase + lf*4;
    const float* xp  = X + (size_t)(c0 + lo)      * LDX + kbase + lf*4;

    float a00=0.f,a10=0.f,a20=0.f,a30=0.f,a01=0.f,a11=0.f,a21=0.f,a31=0.f;

    // prologue: chunk 0 -> buffer 0
    {
        float4 v0 = *(const float4*)(wp0);
        float4 v1 = *(const float4*)(wp1);
        float4 u  = *(const float4*)(xp);
        Ws[0][kk+0][lo]    = v0.x; Ws[0][kk+1][lo]    = v0.y; Ws[0][kk+2][lo]    = v0.z; Ws[0][kk+3][lo]    = v0.w;
        Ws[0][kk+0][lo+32] = v1.x; Ws[0][kk+1][lo+32] = v1.y; Ws[0][kk+2][lo+32] = v1.z; Ws[0][kk+3][lo+32] = v1.w;
        Xs[0][kk+0][lo] = u.x; Xs[0][kk+1][lo] = u.y; Xs[0][kk+2][lo] = u.z; Xs[0][kk+3][lo] = u.w;
    }
    __syncthreads();

    int cur = 0;
    for (int kc = 0; kc < ksteps; ++kc) {
        float4 nv0, nv1, nu;
        const bool more = (kc + 1 < ksteps);
        if (more) {
            nv0 = *(const float4*)(wp0 + (kc+1)*32);
            nv1 = *(const float4*)(wp1 + (kc+1)*32);
            nu  = *(const float4*)(xp  + (kc+1)*32);
        }
        #pragma unroll
        for (int k2 = 0; k2 < 32; ++k2) {
            const float4 a = *(const float4*)&Ws[cur][k2][to*4];
            const float2 b = *(const float2*)&Xs[cur][k2][tc*2];
            a00 = fmaf(a.x, b.x, a00); a10 = fmaf(a.y, b.x, a10);
            a20 = fmaf(a.z, b.x, a20); a30 = fmaf(a.w, b.x, a30);
            a01 = fmaf(a.x, b.y, a01); a11 = fmaf(a.y, b.y, a11);
            a21 = fmaf(a.z, b.y, a21); a31 = fmaf(a.w, b.y, a31);
        }
        if (more) {
            const int nxt = cur ^ 1;
            Ws[nxt][kk+0][lo]    = nv0.x; Ws[nxt][kk+1][lo]    = nv0.y; Ws[nxt][kk+2][lo]    = nv0.z; Ws[nxt][kk+3][lo]    = nv0.w;
            Ws[nxt][kk+0][lo+32] = nv1.x; Ws[nxt][kk+1][lo+32] = nv1.y; Ws[nxt][kk+2][lo+32] = nv1.z; Ws[nxt][kk+3][lo+32] = nv1.w;
            Xs[nxt][kk+0][lo] = nu.x; Xs[nxt][kk+1][lo] = nu.y; Xs[nxt][kk+2][lo] = nu.z; Xs[nxt][kk+3][lo] = nu.w;
            __syncthreads();
            cur = nxt;
        }
    }

    const int col = c0 + tc*2;
    const int o   = o0 + to*4;
    const size_t base = ((size_t)blockIdx.z * (gridDim.y*32) + col) * LDO + o;
    *(float4*)(OUT + base)       = make_float4(a00, a10, a20, a30);
    *(float4*)(OUT + base + LDO) = make_float4(a01, a11, a21, a31);
}

// ---------------------------------------------------------------------------
// Combine 4 split-K partials + exact GELU
// ---------------------------------------------------------------------------
__device__ __forceinline__ float gelu_f(float v) {
    return 0.5f * v * (1.0f + erff(v * 0.70710678118654752f));
}
__global__ __launch_bounds__(256) void k_glu(int n4) {
    int idx = blockIdx.x*256 + threadIdx.x;
    if (idx < n4) {
        const float4* hp = (const float4*)g_hp;
        float4 a = hp[idx];
        float4 b = hp[idx + n4];
        float4 c = hp[idx + 2*n4];
        float4 d = hp[idx + 3*n4];
        float4 r;
        r.x = gelu_f(a.x + b.x + c.x + d.x);
        r.y = gelu_f(a.y + b.y + c.y + d.y);
        r.z = gelu_f(a.z + b.z + c.z + d.z);
        r.w = gelu_f(a.w + b.w + c.w + d.w);
        ((float4*)g_h)[idx] = r;
    }
}

// ---------------------------------------------------------------------------
// Kernel 4: combine GEMM2 partials + sigmoid, masked softmax over adj>0,
// then out = attn @ x (per tile)
// ---------------------------------------------------------------------------
__global__ __launch_bounds__(256) void k_attn(const float* __restrict__ x,
                                              const float* __restrict__ adj,
                                              float* __restrict__ out) {
    __shared__ float xs[32*257];
    __shared__ float at[32*36];     // at[j][i] = attn[i][j]; stride 36 -> 16B aligned rows
    const int tile = blockIdx.x;
    const int tid = threadIdx.x, w = tid >> 5, lane = tid & 31;
    const float* xt = x + (size_t)tile*8192;

    for (int idx = tid; idx < 8192; idx += 256)
        xs[(idx >> 8)*257 + (idx & 255)] = xt[idx];

    const float* e0 = g_ep + (size_t)tile*1024;
    const float* e1 = e0 + (size_t)gridDim.x*1024;
    const float* ar = adj + (size_t)tile*1024;
    #pragma unroll
    for (int k = 0; k < 4; ++k) {
        int i = k*8 + w;
        float a = ar[i*32 + lane];
        float e = e0[i*32 + lane] + e1[i*32 + lane];
        float v = (a > 0.f) ? 1.0f/(1.0f + expf(-e)) : NEGBIG;
        float mx = v;
        #pragma unroll
        for (int off = 16; off; off >>= 1) mx = fmaxf(mx, __shfl_xor_sync(0xffffffffu, mx, off));
        float pv = expf(v - mx);
        float s = pv;
        #pragma unroll
        for (int off = 16; off; off >>= 1) s += __shfl_xor_sync(0xffffffffu, s, off);
        at[lane*36 + i] = pv / s;
    }
    __syncthreads();

    const int c = tid;          // one channel per thread
    float acc[32];
    #pragma unroll
    for (int i = 0; i < 32; ++i) acc[i] = 0.f;
    for (int j = 0; j < 32; ++j) {
        float b = xs[j*257 + c];
        const float4* arow = (const float4*)(at + j*36);   // broadcast loads
        #pragma unroll
        for (int q = 0; q < 8; ++q) {
            float4 aw = arow[q];
            acc[q*4+0] = fmaf(aw.x, b, acc[q*4+0]);
            acc[q*4+1] = fmaf(aw.y, b, acc[q*4+1]);
            acc[q*4+2] = fmaf(aw.z, b, acc[q*4+2]);
            acc[q*4+3] = fmaf(aw.w, b, acc[q*4+3]);
        }
    }
    float* orow = out + (size_t)tile*8192 + c;
    #pragma unroll
    for (int i = 0; i < 32; ++i) orow[i*256] = acc[i];
}

// ---------------------------------------------------------------------------
extern "C" void kernel_launch(void* const* d_in, const int* in_sizes, int n_in,
                              void* d_out, int out_size) {
    const float* x  = (const float*)d_in[0];
    const float* W1 = (const float*)d_in[1];
    const float* W2 = (const float*)d_in[2];
    (void)n_in; (void)out_size;

    int B = in_sizes[0] / (64*32*256);     // = 4
    int tiles = B * 64;                    // = 256
    float* out = (float*)d_out;
    float* adj = out + (size_t)tiles * 8192;   // out first, then adj

    k_stats<<<tiles, 256>>>(x, adj);
    k_gemm<0><<<dim3(8, tiles/32, 4), 256>>>(W1, 8);    // 512x256, K=1024, split-K=4
    int n4 = (tiles*512) / 4;
    k_glu<<<(n4 + 255)/256, 256>>>(n4);
    k_gemm<1><<<dim3(16, tiles/32, 2), 256>>>(W2, 8);   // 1024x256, K=512, split-K=2
    k_attn<<<tiles, 256>>>(x, adj, out);
}

// round 13
// speedup vs baseline: 1.2169x; 1.1378x over previous
#include <cuda_runtime.h>
#include <math.h>

// Shapes fixed by the reference: B=4, M=64, K=32, C=256
//   tiles = B*M = 256 (one per (b,m))
//   p  : [256][1024]    pooled (K*K contiguous per tile)
//   hp : [8][256][512]  split-K partials of W1 @ p
//   h  : [256][512]     gelu(sum hp)
//   ep : [4][256][1024] split-K partials of W2 @ h (sigmoid in k_attn)
// Output buffer = out (B,M,K,C) followed by adj (B,M,K,K).

__device__ float g_p [256*1024];
__device__ float g_hp[8*256*512];
__device__ float g_h [256*512];
__device__ float g_ep[4*256*1024];

#define NEGBIG -9000000000000000.0f

// ---------------------------------------------------------------------------
// Kernel 1 (512 thr): per-tile stats -> adj and pooled -> g_p
// cov_raw_ij = sum_c a*b - 256*mu_i*mu_j ; adj = cov_raw/sqrt(diag_i*diag_j)
// pooled_ij  = 0.5*mu_i + mu_j - (sum_{c: x_i,c==x_j,c} x_j,c)/512
// ---------------------------------------------------------------------------
__global__ __launch_bounds__(512) void k_stats(const float* __restrict__ x,
                                               float* __restrict__ adj) {
    __shared__ float xs[32*257];   // stride 257 -> conflict-free strided access
    __shared__ float mu[32];
    __shared__ float rs[32];
    const int tile = blockIdx.x;
    const int tid  = threadIdx.x;
    const float* xt = x + (size_t)tile * 8192;

    for (int idx = tid; idx < 8192; idx += 512)
        xs[(idx >> 8)*257 + (idx & 255)] = xt[idx];
    __syncthreads();

    // row sums + sumsq: 16 threads per row
    {
        int r = tid >> 4, g = tid & 15;
        const float* row = xs + r*257 + g*16;
        float s = 0.f, s2 = 0.f;
        #pragma unroll
        for (int c = 0; c < 16; ++c) { float v = row[c]; s += v; s2 = fmaf(v, v, s2); }
        #pragma unroll
        for (int off = 8; off; off >>= 1) {
            s  += __shfl_down_sync(0xffffffffu, s,  off, 16);
            s2 += __shfl_down_sync(0xffffffffu, s2, off, 16);
        }
        if (g == 0) {
            float m = s * (1.0f/256.0f);
            mu[r] = m;
            rs[r] = 1.0f / sqrtf(s2 - 256.0f*m*m);
        }
    }
    __syncthreads();

    // pair loop: lane = j; each thread handles i in {w, w+16}
    const int w = tid >> 5, lane = tid & 31;
    const float* rowj = xs + lane*257;
    const float muj = mu[lane];
    const float rsj = rs[lane];

    float sab[2] = {0.f,0.f};
    float eqs[2] = {0.f,0.f};
    #pragma unroll 8
    for (int c = 0; c < 256; ++c) {
        float b = rowj[c];
        #pragma unroll
        for (int k = 0; k < 2; ++k) {
            float a = xs[(k*16 + w)*257 + c];   // warp-uniform broadcast
            sab[k] = fmaf(a, b, sab[k]);
            if (a == b) eqs[k] += b;            // exact equality (pos mask)
        }
    }
    #pragma unroll
    for (int k = 0; k < 2; ++k) {
        int i = k*16 + w;
        float mui = mu[i];
        float covraw = sab[k] - 256.0f*mui*muj;
        int o = i*32 + lane;
        adj[(size_t)tile*1024 + o] = covraw * rs[i] * rsj;
        g_p[(size_t)tile*1024 + o] = fmaf(eqs[k], -(1.0f/512.0f), 0.5f*mui + muj);
    }
}

// ---------------------------------------------------------------------------
// Tiled SGEMM, double-buffered SMEM, split-K along blockIdx.z.
// Block tile 64(o) x 64(col), 256 threads, micro 4x4. k-transposed SMEM.
// EPI==0: GEMM1 partial (X=g_p, OUT=g_hp, ld=1024, ldo=512)
// EPI==1: GEMM2 partial (X=g_h, OUT=g_ep, ld=512,  ldo=1024)
// ---------------------------------------------------------------------------
template<int EPI>
__global__ __launch_bounds__(256) void k_gemm(const float* __restrict__ W, int ksteps) {
    __shared__ float Ws[2][32][68];
    __shared__ float Xs[2][32][68];
    constexpr int LDW = (EPI == 0) ? 1024 : 512;
    constexpr int LDX = (EPI == 0) ? 1024 : 512;
    constexpr int LDO = (EPI == 0) ? 512  : 1024;
    const float* X   = (EPI == 0) ? g_p  : g_h;
    float*       OUT = (EPI == 0) ? g_hp : g_ep;

    const int tid = threadIdx.x;
    const int o0 = blockIdx.x*64, c0 = blockIdx.y*64;
    const int kbase = blockIdx.z * (ksteps*32);
    const int to = tid & 15, tc = tid >> 4;   // micro: o=o0+to*4+{0..3}, col=c0+tc*4+{0..3}
    const int lo = tid >> 3, lf = tid & 7;    // loaders
    const int kk = lf*4;

    const float* wp0 = W + (size_t)(o0 + lo)      * LDW + kbase + lf*4;
    const float* wp1 = W + (size_t)(o0 + lo + 32) * LDW + kbase + lf*4;
    const float* xp0 = X + (size_t)(c0 + lo)      * LDX + kbase + lf*4;
    const float* xp1 = X + (size_t)(c0 + lo + 32) * LDX + kbase + lf*4;

    float acc[4][4];
    #pragma unroll
    for (int i = 0; i < 4; ++i)
        #pragma unroll
        for (int j = 0; j < 4; ++j) acc[i][j] = 0.f;

    // prologue: chunk 0 -> buffer 0
    {
        float4 v0 = *(const float4*)(wp0);
        float4 v1 = *(const float4*)(wp1);
        float4 u0 = *(const float4*)(xp0);
        float4 u1 = *(const float4*)(xp1);
        Ws[0][kk+0][lo]    = v0.x; Ws[0][kk+1][lo]    = v0.y; Ws[0][kk+2][lo]    = v0.z; Ws[0][kk+3][lo]    = v0.w;
        Ws[0][kk+0][lo+32] = v1.x; Ws[0][kk+1][lo+32] = v1.y; Ws[0][kk+2][lo+32] = v1.z; Ws[0][kk+3][lo+32] = v1.w;
        Xs[0][kk+0][lo]    = u0.x; Xs[0][kk+1][lo]    = u0.y; Xs[0][kk+2][lo]    = u0.z; Xs[0][kk+3][lo]    = u0.w;
        Xs[0][kk+0][lo+32] = u1.x; Xs[0][kk+1][lo+32] = u1.y; Xs[0][kk+2][lo+32] = u1.z; Xs[0][kk+3][lo+32] = u1.w;
    }
    __syncthreads();

    int cur = 0;
    for (int kc = 0; kc < ksteps; ++kc) {
        float4 nv0, nv1, nu0, nu1;
        const bool more = (kc + 1 < ksteps);
        if (more) {
            nv0 = *(const float4*)(wp0 + (kc+1)*32);
            nv1 = *(const float4*)(wp1 + (kc+1)*32);
            nu0 = *(const float4*)(xp0 + (kc+1)*32);
            nu1 = *(const float4*)(xp1 + (kc+1)*32);
        }
        #pragma unroll
        for (int k2 = 0; k2 < 32; ++k2) {
            const float4 a = *(const float4*)&Ws[cur][k2][to*4];
            const float4 b = *(const float4*)&Xs[cur][k2][tc*4];
            acc[0][0] = fmaf(a.x, b.x, acc[0][0]); acc[1][0] = fmaf(a.y, b.x, acc[1][0]);
            acc[2][0] = fmaf(a.z, b.x, acc[2][0]); acc[3][0] = fmaf(a.w, b.x, acc[3][0]);
            acc[0][1] = fmaf(a.x, b.y, acc[0][1]); acc[1][1] = fmaf(a.y, b.y, acc[1][1]);
            acc[2][1] = fmaf(a.z, b.y, acc[2][1]); acc[3][1] = fmaf(a.w, b.y, acc[3][1]);
            acc[0][2] = fmaf(a.x, b.z, acc[0][2]); acc[1][2] = fmaf(a.y, b.z, acc[1][2]);
            acc[2][2] = fmaf(a.z, b.z, acc[2][2]); acc[3][2] = fmaf(a.w, b.z, acc[3][2]);
            acc[0][3] = fmaf(a.x, b.w, acc[0][3]); acc[1][3] = fmaf(a.y, b.w, acc[1][3]);
            acc[2][3] = fmaf(a.z, b.w, acc[2][3]); acc[3][3] = fmaf(a.w, b.w, acc[3][3]);
        }
        if (more) {
            const int nxt = cur ^ 1;
            Ws[nxt][kk+0][lo]    = nv0.x; Ws[nxt][kk+1][lo]    = nv0.y; Ws[nxt][kk+2][lo]    = nv0.z; Ws[nxt][kk+3][lo]    = nv0.w;
            Ws[nxt][kk+0][lo+32] = nv1.x; Ws[nxt][kk+1][lo+32] = nv1.y; Ws[nxt][kk+2][lo+32] = nv1.z; Ws[nxt][kk+3][lo+32] = nv1.w;
            Xs[nxt][kk+0][lo]    = nu0.x; Xs[nxt][kk+1][lo]    = nu0.y; Xs[nxt][kk+2][lo]    = nu0.z; Xs[nxt][kk+3][lo]    = nu0.w;
            Xs[nxt][kk+0][lo+32] = nu1.x; Xs[nxt][kk+1][lo+32] = nu1.y; Xs[nxt][kk+2][lo+32] = nu1.z; Xs[nxt][kk+3][lo+32] = nu1.w;
            __syncthreads();
            cur = nxt;
        }
    }

    const int col = c0 + tc*4;
    const int o   = o0 + to*4;
    const size_t base = ((size_t)blockIdx.z * (gridDim.y*64) + col) * LDO + o;
    #pragma unroll
    for (int j = 0; j < 4; ++j)
        *(float4*)(OUT + base + (size_t)j*LDO) =
            make_float4(acc[0][j], acc[1][j], acc[2][j], acc[3][j]);
}

// ---------------------------------------------------------------------------
// Combine 8 split-K partials + exact GELU
// ---------------------------------------------------------------------------
__device__ __forceinline__ float gelu_f(float v) {
    return 0.5f * v * (1.0f + erff(v * 0.70710678118654752f));
}
__global__ __launch_bounds__(256) void k_glu(int n4) {
    int idx = blockIdx.x*256 + threadIdx.x;
    if (idx < n4) {
        const float4* hp = (const float4*)g_hp;
        float sx = 0.f, sy = 0.f, sz = 0.f, sw = 0.f;
        #pragma unroll
        for (int t = 0; t < 8; ++t) {
            float4 a = hp[idx + t*n4];
            sx += a.x; sy += a.y; sz += a.z; sw += a.w;
        }
        ((float4*)g_h)[idx] = make_float4(gelu_f(sx), gelu_f(sy), gelu_f(sz), gelu_f(sw));
    }
}

// ---------------------------------------------------------------------------
// Kernel 4 (512 thr): combine GEMM2 partials + sigmoid, masked softmax over
// adj>0, then out = attn @ x (per tile)
// ---------------------------------------------------------------------------
__global__ __launch_bounds__(512) void k_attn(const float* __restrict__ x,
                                              const float* __restrict__ adj,
                                              float* __restrict__ out) {
    __shared__ float xs[32*257];
    __shared__ float at[32*36];     // at[j][i] = attn[i][j]
    const int tile = blockIdx.x;
    const int tid = threadIdx.x, w = tid >> 5, lane = tid & 31;
    const float* xt = x + (size_t)tile*8192;

    for (int idx = tid; idx < 8192; idx += 512)
        xs[(idx >> 8)*257 + (idx & 255)] = xt[idx];

    const float* e0 = g_ep + (size_t)tile*1024;
    const float* ar = adj + (size_t)tile*1024;
    #pragma unroll
    for (int k = 0; k < 2; ++k) {
        int i = k*16 + w;
        int o = i*32 + lane;
        float a = ar[o];
        float e = e0[o] + e0[o + 256*1024] + e0[o + 2*256*1024] + e0[o + 3*256*1024];
        float v = (a > 0.f) ? 1.0f/(1.0f + expf(-e)) : NEGBIG;
        float mx = v;
        #pragma unroll
        for (int off = 16; off; off >>= 1) mx = fmaxf(mx, __shfl_xor_sync(0xffffffffu, mx, off));
        float pv = expf(v - mx);
        float s = pv;
        #pragma unroll
        for (int off = 16; off; off >>= 1) s += __shfl_xor_sync(0xffffffffu, s, off);
        at[lane*36 + i] = pv / s;
    }
    __syncthreads();

    // each half of the block handles 16 of the 32 output rows, one channel/thread
    const int c = tid & 255;
    const int half = tid >> 8;          // 0 or 1
    float acc[16];
    #pragma unroll
    for (int i = 0; i < 16; ++i) acc[i] = 0.f;
    for (int j = 0; j < 32; ++j) {
        float b = xs[j*257 + c];
        const float4* arow = (const float4*)(at + j*36 + half*16);   // broadcast loads
        #pragma unroll
        for (int q = 0; q < 4; ++q) {
            float4 aw = arow[q];
            acc[q*4+0] = fmaf(aw.x, b, acc[q*4+0]);
            acc[q*4+1] = fmaf(aw.y, b, acc[q*4+1]);
            acc[q*4+2] = fmaf(aw.z, b, acc[q*4+2]);
            acc[q*4+3] = fmaf(aw.w, b, acc[q*4+3]);
        }
    }
    float* orow = out + (size_t)tile*8192 + (half*16)*256 + c;
    #pragma unroll
    for (int i = 0; i < 16; ++i) orow[i*256] = acc[i];
}

// ---------------------------------------------------------------------------
extern "C" void kernel_launch(void* const* d_in, const int* in_sizes, int n_in,
                              void* d_out, int out_size) {
    const float* x  = (const float*)d_in[0];
    const float* W1 = (const float*)d_in[1];
    const float* W2 = (const float*)d_in[2];
    (void)n_in; (void)out_size;

    int B = in_sizes[0] / (64*32*256);     // = 4
    int tiles = B * 64;                    // = 256
    float* out = (float*)d_out;
    float* adj = out + (size_t)tiles * 8192;   // out first, then adj

    k_stats<<<tiles, 512>>>(x, adj);
    k_gemm<0><<<dim3(8, tiles/64, 8), 256>>>(W1, 4);    // 512x256, K=1024, split-K=8
    int n4 = (tiles*512) / 4;
    k_glu<<<(n4 + 255)/256, 256>>>(n4);
    k_gemm<1><<<dim3(16, tiles/64, 4), 256>>>(W2, 4);   // 1024x256, K=512, split-K=4
    k_attn<<<tiles, 512>>>(x, adj, out);
}